// round 13
// baseline (speedup 1.0000x reference)
#include <cuda_runtime.h>
#include <math.h>

#define B 32
#define H 512
#define E 256
#define VV 32000
#define TT 64
#define KF 768          // E + H (per-step feature length)
#define WOUT_LD 1280    // 2H + E
#define PADZ 516        // H + 4 pad (baseK only)
#define WT2 12          // logits weight tile row stride (8 + 4): 48B = 3x16B, conflict-free

typedef unsigned long long u64;

// ---------------- persistent device scratch (no allocations) ----------------
__device__ float d_scratch[TT * B * VV];        // logits in (T, B, V) layout
__device__ float d_base[B * VV];                // z @ W_out_z^T + b_out
__device__ float d_cg[4 * H * B];               // z @ W_ih_z^T + b_ih + b_hh, [R][b]
__device__ float d_hbuf[2][B * H];              // double-buffered hidden state
__device__ float d_cbuf[B * H];                 // cell state
__device__ u64 d_slot[TT * B];                  // packed (orderable(max) << 32) | ~argmax

__device__ __forceinline__ u64 packmax(float f, int v) {
    unsigned u = __float_as_uint(f);
    u = (u & 0x80000000u) ? ~u : (u | 0x80000000u);   // order-preserving float->uint
    return ((u64)u << 32) | (unsigned)(~v);           // ties -> smallest v wins
}

__device__ __forceinline__ float sigmoidf_(float x) { return 1.0f / (1.0f + expf(-x)); }

// Packed fp32x2 FMA (Blackwell)
__device__ __forceinline__ u64 fma2(u64 a, u64 b, u64 c) {
    u64 d;
    asm("fma.rn.f32x2 %0, %1, %2, %3;" : "=l"(d) : "l"(a), "l"(b), "l"(c));
    return d;
}
__device__ __forceinline__ float2 u2f(u64 v) {
    float2 r;
    asm("mov.b64 {%0, %1}, %2;" : "=f"(r.x), "=f"(r.y) : "l"(v));
    return r;
}
// 16B shared load as two u64 k-pairs
__device__ __forceinline__ void lds128(u64& a, u64& b, unsigned saddr) {
    asm("ld.shared.v2.u64 {%0, %1}, [%2];" : "=l"(a), "=l"(b) : "r"(saddr));
}

// ---------------- init ----------------
__global__ void initK(const float* __restrict__ h0, const float* __restrict__ c0) {
    int i = blockIdx.x * blockDim.x + threadIdx.x;
    if (i < B * H) { d_hbuf[0][i] = h0[i]; d_cbuf[i] = c0[i]; }
    if (i < TT * B) d_slot[i] = 0ULL;
}

// ---------------- precompute cg[R][b] = z[b].W_ih[R,:512] + b_ih + b_hh ----------------
__global__ void constgateK(const float* __restrict__ h0, const float* __restrict__ Wih,
                           const float* __restrict__ bih, const float* __restrict__ bhh) {
    int gw = (blockIdx.x * blockDim.x + threadIdx.x) >> 5;
    int lane = threadIdx.x & 31;
    int b = gw & 31;
    int R = gw >> 5;
    const float* z = h0 + b * H;
    const float* w = Wih + (long)R * KF;
    float a = 0.f;
    for (int k = lane; k < H; k += 32) a += w[k] * z[k];
    #pragma unroll
    for (int o = 16; o > 0; o >>= 1) a += __shfl_down_sync(0xffffffffu, a, o);
    if (lane == 0) d_cg[R * B + b] = a + bih[R] + bhh[R];
}

// ---------------- precompute base[b][v] = z[b].W_out[v,:512] + b_out[v] ----------------
__global__ __launch_bounds__(128, 2) void baseK(const float* __restrict__ h0,
        const float* __restrict__ Wout, const float* __restrict__ bout) {
    extern __shared__ float zs[];   // B * PADZ floats
    int tid = threadIdx.x;
    for (int i = tid; i < B * (H / 4); i += 128) {
        int b = i / (H / 4), k = (i % (H / 4)) * 4;
        *(float4*)(zs + b * PADZ + k) = *(const float4*)(h0 + b * H + k);
    }
    __syncthreads();
    int warp = tid >> 5, lane = tid & 31;
    int v = blockIdx.x * 128 + warp * 32 + lane;
    const float* wrow = Wout + (long)v * WOUT_LD;     // cols [0:512)
    u64 acc[32];
    #pragma unroll
    for (int i = 0; i < 32; i++) acc[i] = 0ULL;
    unsigned zsb = (unsigned)__cvta_generic_to_shared(zs);
    for (int kb = 0; kb < H; kb += 16) {
        ulonglong2 w[4];
        #pragma unroll
        for (int i = 0; i < 4; i++) w[i] = *(const ulonglong2*)(wrow + kb + i * 4);
        #pragma unroll
        for (int i = 0; i < 4; i++) {
            #pragma unroll
            for (int b = 0; b < 32; b++) {
                u64 fa, fb;
                lds128(fa, fb, zsb + (unsigned)(b * PADZ + kb + i * 4) * 4u);
                acc[b] = fma2(w[i].x, fa, acc[b]);
                acc[b] = fma2(w[i].y, fb, acc[b]);
            }
        }
    }
    float bo = bout[v];
    #pragma unroll
    for (int b = 0; b < 32; b++) {
        float2 p = u2f(acc[b]);
        d_base[(long)b * VV + v] = p.x + p.y + bo;
    }
}

// ---------------- per-step fused LSTM gates ----------------
// 128 blocks x 256 thr. Block: 4 j x 4 gates = 16 rows; lane = row*2 + b-half.
// Warps split K 8 ways (96 k); chunk-16 with cross-chunk register double-buffer.
__global__ __launch_bounds__(256) void gatesF(int t, const int* __restrict__ y0,
        const float* __restrict__ emb, const float* __restrict__ Wih,
        const float* __restrict__ Whh) {
    extern __shared__ float fs[];                 // B*768 feat | 8*528 partials
    float* part = fs + B * 768;
    int* ys = (int*)part;                         // alias: used before part written
    int tid = threadIdx.x;
    if (tid < B)
        ys[tid] = (t == 0) ? y0[tid]
                           : (int)(~(unsigned)(d_slot[(t - 1) * B + tid] & 0xFFFFFFFFull));
    __syncthreads();
    const float* hold = d_hbuf[t & 1];
    for (int i = tid; i < B * (KF / 4); i += 256) {
        int b = i / (KF / 4), k = (i % (KF / 4)) * 4;
        float4 v = (k < E) ? *(const float4*)(emb + (long)ys[b] * E + k)
                           : *(const float4*)(hold + b * H + (k - E));
        *(float4*)(fs + b * 768 + k) = v;
    }
    __syncthreads();
    int warp = tid >> 5, lane = tid & 31;
    int row = lane >> 1, bh = lane & 1, b0 = bh << 4;
    int g = row >> 2, jl = row & 3;
    int j = blockIdx.x * 4 + jl;
    int R = g * H + j;
    int klo = warp * 96;
    u64 acc[16];
    #pragma unroll
    for (int i = 0; i < 16; i++) acc[i] = 0ULL;
    unsigned fsb = (unsigned)__cvta_generic_to_shared(fs);
    const float* w1  = Wih + (long)R * KF + 512;      // k in [0,256): emb part
    const float* w2p = Whh + (long)R * H - E;         // k in [256,768): h part
    // 96-k segment = 6 chunks of 16; chunks never straddle E=256 (all bounds x16).
    // Weights double-buffered in regs: next chunk's 4 LDG issued before compute.
    ulonglong2 w[4], wn[4];
    {
        const float* wp = (klo < E) ? (w1 + klo) : (w2p + klo);
        #pragma unroll
        for (int i = 0; i < 4; i++) w[i] = *(const ulonglong2*)(wp + i * 4);
    }
    for (int kc = klo; kc < klo + 96; kc += 16) {
        int kn = kc + 16;
        if (kn < klo + 96) {
            const float* wq = (kn < E) ? (w1 + kn) : (w2p + kn);
            #pragma unroll
            for (int i = 0; i < 4; i++) wn[i] = *(const ulonglong2*)(wq + i * 4);
        }
        #pragma unroll
        for (int i = 0; i < 4; i++) {
            #pragma unroll
            for (int bb = 0; bb < 16; bb++) {
                u64 fa, fb;
                lds128(fa, fb, fsb + (unsigned)((b0 + bb) * 768 + kc + i * 4) * 4u);
                acc[bb] = fma2(w[i].x, fa, acc[bb]);
                acc[bb] = fma2(w[i].y, fb, acc[bb]);
            }
        }
        #pragma unroll
        for (int i = 0; i < 4; i++) w[i] = wn[i];
    }
    #pragma unroll
    for (int bb = 0; bb < 16; bb++) {
        float2 p = u2f(acc[bb]);
        part[warp * 528 + row * 33 + b0 + bb] = p.x + p.y;
    }
    __syncthreads();
    // pointwise: thread = (jj, b) for 4 j x 32 b
    if (tid < 128) {
        int jj = tid >> 5, b = tid & 31;
        float gv[4];
        #pragma unroll
        for (int g2 = 0; g2 < 4; g2++) {
            int ln = g2 * 4 + jj;
            float s = 0.f;
            #pragma unroll
            for (int w2 = 0; w2 < 8; w2++) s += part[w2 * 528 + ln * 33 + b];
            gv[g2] = s + d_cg[(g2 * H + blockIdx.x * 4 + jj) * B + b];
        }
        float ig = sigmoidf_(gv[0]);
        float fg = sigmoidf_(gv[1]);
        float gg = tanhf(gv[2]);
        float og = sigmoidf_(gv[3]);
        int jg = blockIdx.x * 4 + jj;
        float c = fg * d_cbuf[b * H + jg] + ig * gg;
        d_cbuf[b * H + jg] = c;
        d_hbuf[(t + 1) & 1][b * H + jg] = og * tanhf(c);
    }
}

// ---------------- per-step logits (K=768 part) + fused argmax ----------------
// 500 blocks x 128 thr, 4 blocks/SM (16 warps/SM). Block = 16 b x 128 v, full K.
// Weights staged per 8-k chunk through smem (coalesced LDG, reg-pipelined).
__global__ __launch_bounds__(128, 4) void logitsK(int t, const int* __restrict__ y0,
        const float* __restrict__ emb, const float* __restrict__ Wout) {
    extern __shared__ float fs[];                 // 16*768 feat | 128*WT2 weight tile
    float* wt = fs + 16 * 768;
    int* ys = (int*)wt;                           // alias: dead before wt written
    u64* red = (u64*)wt;                          // alias: wt dead after final chunk sync
    int tid = threadIdx.x;
    int vt = blockIdx.x >> 1, bhf = blockIdx.x & 1, b0 = bhf << 4;
    if (tid < B)
        ys[tid] = (t == 0) ? y0[tid]
                           : (int)(~(unsigned)(d_slot[(t - 1) * B + tid] & 0xFFFFFFFFull));
    __syncthreads();
    const float* hc = d_hbuf[(t + 1) & 1];
    for (int i = tid; i < 16 * (KF / 4); i += 128) {
        int b = i / (KF / 4), k = (i % (KF / 4)) * 4;
        int gb = b0 + b;
        float4 v = (k < E) ? *(const float4*)(emb + (long)ys[gb] * E + k)
                           : *(const float4*)(hc + gb * H + (k - E));
        *(float4*)(fs + b * 768 + k) = v;
    }
    __syncthreads();                              // ys reads done; wt region free
    int warp = tid >> 5, lane = tid & 31;
    int vl = warp * 32 + lane;
    int v = vt * 128 + vl;
    // tile: 128 rows x 8 floats = 256 float4s; thread loads rows tid>>1 and 64+(tid>>1)
    int q = tid & 1;
    int r0 = tid >> 1;
    const float* g1 = Wout + ((long)vt * 128 + r0) * WOUT_LD + 512 + q * 4;
    const float* g2 = g1 + 64 * WOUT_LD;
    float* s1 = wt + r0 * WT2 + q * 4;
    float* s2 = s1 + 64 * WT2;
    u64 acc[16];
    #pragma unroll
    for (int i = 0; i < 16; i++) acc[i] = 0ULL;
    unsigned fsb = (unsigned)__cvta_generic_to_shared(fs);
    unsigned wlb = (unsigned)__cvta_generic_to_shared(wt + vl * WT2);
    float4 p1 = *(const float4*)(g1);             // preload chunk 0
    float4 p2 = *(const float4*)(g2);
    for (int kb = 0; kb < KF; kb += 8) {
        *(float4*)s1 = p1;
        *(float4*)s2 = p2;
        __syncthreads();
        if (kb + 8 < KF) {                        // prefetch next chunk into regs
            p1 = *(const float4*)(g1 + kb + 8);
            p2 = *(const float4*)(g2 + kb + 8);
        }
        #pragma unroll
        for (int i = 0; i < 2; i++) {
            u64 wx, wy;
            lds128(wx, wy, wlb + (unsigned)(i * 16));
            #pragma unroll
            for (int b = 0; b < 16; b++) {
                u64 fa, fb;
                lds128(fa, fb, fsb + (unsigned)(b * 768 + kb + i * 4) * 4u);
                acc[b] = fma2(wx, fa, acc[b]);
                acc[b] = fma2(wy, fb, acc[b]);
            }
        }
        __syncthreads();
    }
    // epilogue: add base, store (T,B,V), per-b argmax across 128 v in block
    #pragma unroll
    for (int b = 0; b < 16; b++) {
        int gb = b0 + b;
        float2 p = u2f(acc[b]);
        float s = p.x + p.y + d_base[(long)gb * VV + v];
        d_scratch[((long)t * B + gb) * VV + v] = s;
        u64 pm = packmax(s, v);
        #pragma unroll
        for (int o = 16; o > 0; o >>= 1) {
            u64 qq = __shfl_xor_sync(0xffffffffu, pm, o);
            if (qq > pm) pm = qq;
        }
        if (lane == 0) red[warp * 16 + b] = pm;
    }
    __syncthreads();
    if (tid < 16) {
        u64 m = red[tid];
        #pragma unroll
        for (int w = 1; w < 4; w++) if (red[w * 16 + tid] > m) m = red[w * 16 + tid];
        atomicMax(&d_slot[t * B + b0 + tid], m);
    }
}

// ---------------- final transpose (T, B, V) -> (B, V, T) ----------------
__global__ void transposeK(float* __restrict__ out) {
    __shared__ float tile[32][33];
    int b  = blockIdx.z;
    int vt = blockIdx.x;
    int tt = blockIdx.y;
    int tx = threadIdx.x, ty = threadIdx.y;   // (32, 8)
    #pragma unroll
    for (int i = 0; i < 32; i += 8) {
        int t = tt * 32 + ty + i;
        int v = vt * 32 + tx;
        tile[ty + i][tx] = d_scratch[((long)t * B + b) * VV + v];
    }
    __syncthreads();
    #pragma unroll
    for (int i = 0; i < 32; i += 8) {
        int v = vt * 32 + ty + i;
        int t = tt * 32 + tx;
        out[((long)b * VV + v) * TT + t] = tile[tx][ty + i];
    }
}

// ---------------- launch ----------------
extern "C" void kernel_launch(void* const* d_in, const int* in_sizes, int n_in,
                              void* d_out, int out_size) {
    const int*   y0   = (const int*)d_in[0];
    const float* h0   = (const float*)d_in[1];
    const float* c0   = (const float*)d_in[2];
    const float* emb  = (const float*)d_in[3];
    const float* Wih  = (const float*)d_in[4];
    const float* Whh  = (const float*)d_in[5];
    const float* bih  = (const float*)d_in[6];
    const float* bhh  = (const float*)d_in[7];
    const float* Wout = (const float*)d_in[8];
    const float* bout = (const float*)d_in[9];
    float* out = (float*)d_out;

    int smemL = (16 * 768 + 128 * WT2) * (int)sizeof(float);  // 55296 B -> 4 blocks/SM
    int smemG = (B * 768 + 8 * 528) * (int)sizeof(float);     // 115200 B
    int smemB = B * PADZ * (int)sizeof(float);                // 66048 B
    cudaFuncSetAttribute(logitsK, cudaFuncAttributeMaxDynamicSharedMemorySize, smemL);
    cudaFuncSetAttribute(gatesF,  cudaFuncAttributeMaxDynamicSharedMemorySize, smemG);
    cudaFuncSetAttribute(baseK,   cudaFuncAttributeMaxDynamicSharedMemorySize, smemB);

    initK<<<64, 256>>>(h0, c0);
    constgateK<<<8192, 256>>>(h0, Wih, bih, bhh);
    baseK<<<VV / 128, 128, smemB>>>(h0, Wout, bout);

    for (int t = 0; t < TT; t++) {
        gatesF<<<128, 256, smemG>>>(t, y0, emb, Wih, Whh);
        logitsK<<<VV / 64, 128, smemL>>>(t, y0, emb, Wout);   // 500 blocks (v-tile x b-half)
    }
    transposeK<<<dim3(VV / 32, TT / 32, B), dim3(32, 8)>>>(out);
}

// round 14
// speedup vs baseline: 1.2570x; 1.2570x over previous
#include <cuda_runtime.h>
#include <math.h>

#define B 32
#define H 512
#define E 256
#define VV 32000
#define TT 64
#define KF 768          // E + H (per-step feature length)
#define WOUT_LD 1280    // 2H + E
#define PADZ 516        // H + 4 pad (baseK only)
#define WTLD 20         // weight tile row stride (16 + 4): 80B = odd multiple of 16B

typedef unsigned long long u64;

// ---------------- persistent device scratch (no allocations) ----------------
__device__ float d_scratch[TT * B * VV];        // logits in (T, B, V) layout
__device__ float d_base[B * VV];                // z @ W_out_z^T + b_out
__device__ float d_cg[4 * H * B];               // z @ W_ih_z^T + b_ih + b_hh, [R][b]
__device__ float d_hbuf[2][B * H];              // double-buffered hidden state
__device__ float d_cbuf[B * H];                 // cell state
__device__ u64 d_slot[TT * B];                  // packed (orderable(max) << 32) | ~argmax

__device__ __forceinline__ u64 packmax(float f, int v) {
    unsigned u = __float_as_uint(f);
    u = (u & 0x80000000u) ? ~u : (u | 0x80000000u);   // order-preserving float->uint
    return ((u64)u << 32) | (unsigned)(~v);           // ties -> smallest v wins
}

__device__ __forceinline__ float sigmoidf_(float x) { return 1.0f / (1.0f + expf(-x)); }

// Packed fp32x2 FMA (Blackwell)
__device__ __forceinline__ u64 fma2(u64 a, u64 b, u64 c) {
    u64 d;
    asm("fma.rn.f32x2 %0, %1, %2, %3;" : "=l"(d) : "l"(a), "l"(b), "l"(c));
    return d;
}
__device__ __forceinline__ float2 u2f(u64 v) {
    float2 r;
    asm("mov.b64 {%0, %1}, %2;" : "=f"(r.x), "=f"(r.y) : "l"(v));
    return r;
}
// 16B shared load as two u64 k-pairs
__device__ __forceinline__ void lds128(u64& a, u64& b, unsigned saddr) {
    asm("ld.shared.v2.u64 {%0, %1}, [%2];" : "=l"(a), "=l"(b) : "r"(saddr));
}

// ---------------- init ----------------
__global__ void initK(const float* __restrict__ h0, const float* __restrict__ c0) {
    int i = blockIdx.x * blockDim.x + threadIdx.x;
    if (i < B * H) { d_hbuf[0][i] = h0[i]; d_cbuf[i] = c0[i]; }
    if (i < TT * B) d_slot[i] = 0ULL;
}

// ---------------- precompute cg[R][b] = z[b].W_ih[R,:512] + b_ih + b_hh ----------------
__global__ void constgateK(const float* __restrict__ h0, const float* __restrict__ Wih,
                           const float* __restrict__ bih, const float* __restrict__ bhh) {
    int gw = (blockIdx.x * blockDim.x + threadIdx.x) >> 5;
    int lane = threadIdx.x & 31;
    int b = gw & 31;
    int R = gw >> 5;
    const float* z = h0 + b * H;
    const float* w = Wih + (long)R * KF;
    float a = 0.f;
    for (int k = lane; k < H; k += 32) a += w[k] * z[k];
    #pragma unroll
    for (int o = 16; o > 0; o >>= 1) a += __shfl_down_sync(0xffffffffu, a, o);
    if (lane == 0) d_cg[R * B + b] = a + bih[R] + bhh[R];
}

// ---------------- precompute base[b][v] = z[b].W_out[v,:512] + b_out[v] ----------------
__global__ __launch_bounds__(128, 2) void baseK(const float* __restrict__ h0,
        const float* __restrict__ Wout, const float* __restrict__ bout) {
    extern __shared__ float zs[];   // B * PADZ floats
    int tid = threadIdx.x;
    for (int i = tid; i < B * (H / 4); i += 128) {
        int b = i / (H / 4), k = (i % (H / 4)) * 4;
        *(float4*)(zs + b * PADZ + k) = *(const float4*)(h0 + b * H + k);
    }
    __syncthreads();
    int warp = tid >> 5, lane = tid & 31;
    int v = blockIdx.x * 128 + warp * 32 + lane;
    const float* wrow = Wout + (long)v * WOUT_LD;     // cols [0:512)
    u64 acc[32];
    #pragma unroll
    for (int i = 0; i < 32; i++) acc[i] = 0ULL;
    unsigned zsb = (unsigned)__cvta_generic_to_shared(zs);
    for (int kb = 0; kb < H; kb += 16) {
        ulonglong2 w[4];
        #pragma unroll
        for (int i = 0; i < 4; i++) w[i] = *(const ulonglong2*)(wrow + kb + i * 4);
        #pragma unroll
        for (int i = 0; i < 4; i++) {
            #pragma unroll
            for (int b = 0; b < 32; b++) {
                u64 fa, fb;
                lds128(fa, fb, zsb + (unsigned)(b * PADZ + kb + i * 4) * 4u);
                acc[b] = fma2(w[i].x, fa, acc[b]);
                acc[b] = fma2(w[i].y, fb, acc[b]);
            }
        }
    }
    float bo = bout[v];
    #pragma unroll
    for (int b = 0; b < 32; b++) {
        float2 p = u2f(acc[b]);
        d_base[(long)b * VV + v] = p.x + p.y + bo;
    }
}

// ---------------- per-step fused LSTM gates ----------------
// 128 blocks x 256 thr. Block: 4 j x 4 gates = 16 rows; lane = row*2 + b-half.
// Warps split K 8 ways (96 k); chunk-16 with cross-chunk register double-buffer.
__global__ __launch_bounds__(256) void gatesF(int t, const int* __restrict__ y0,
        const float* __restrict__ emb, const float* __restrict__ Wih,
        const float* __restrict__ Whh) {
    extern __shared__ float fs[];                 // B*768 feat | 8*528 partials
    float* part = fs + B * 768;
    int* ys = (int*)part;                         // alias: used before part written
    int tid = threadIdx.x;
    if (tid < B)
        ys[tid] = (t == 0) ? y0[tid]
                           : (int)(~(unsigned)(d_slot[(t - 1) * B + tid] & 0xFFFFFFFFull));
    __syncthreads();
    const float* hold = d_hbuf[t & 1];
    for (int i = tid; i < B * (KF / 4); i += 256) {
        int b = i / (KF / 4), k = (i % (KF / 4)) * 4;
        float4 v = (k < E) ? *(const float4*)(emb + (long)ys[b] * E + k)
                           : *(const float4*)(hold + b * H + (k - E));
        *(float4*)(fs + b * 768 + k) = v;
    }
    __syncthreads();
    int warp = tid >> 5, lane = tid & 31;
    int row = lane >> 1, bh = lane & 1, b0 = bh << 4;
    int g = row >> 2, jl = row & 3;
    int j = blockIdx.x * 4 + jl;
    int R = g * H + j;
    int klo = warp * 96;
    u64 acc[16];
    #pragma unroll
    for (int i = 0; i < 16; i++) acc[i] = 0ULL;
    unsigned fsb = (unsigned)__cvta_generic_to_shared(fs);
    const float* w1  = Wih + (long)R * KF + 512;      // k in [0,256): emb part
    const float* w2p = Whh + (long)R * H - E;         // k in [256,768): h part
    // 96-k segment = 6 chunks of 16; chunks never straddle E=256 (all bounds x16).
    // Weights double-buffered in regs: next chunk's 4 LDG issued before compute.
    ulonglong2 w[4], wn[4];
    {
        const float* wp = (klo < E) ? (w1 + klo) : (w2p + klo);
        #pragma unroll
        for (int i = 0; i < 4; i++) w[i] = *(const ulonglong2*)(wp + i * 4);
    }
    for (int kc = klo; kc < klo + 96; kc += 16) {
        int kn = kc + 16;
        if (kn < klo + 96) {
            const float* wq = (kn < E) ? (w1 + kn) : (w2p + kn);
            #pragma unroll
            for (int i = 0; i < 4; i++) wn[i] = *(const ulonglong2*)(wq + i * 4);
        }
        #pragma unroll
        for (int i = 0; i < 4; i++) {
            #pragma unroll
            for (int bb = 0; bb < 16; bb++) {
                u64 fa, fb;
                lds128(fa, fb, fsb + (unsigned)((b0 + bb) * 768 + kc + i * 4) * 4u);
                acc[bb] = fma2(w[i].x, fa, acc[bb]);
                acc[bb] = fma2(w[i].y, fb, acc[bb]);
            }
        }
        #pragma unroll
        for (int i = 0; i < 4; i++) w[i] = wn[i];
    }
    #pragma unroll
    for (int bb = 0; bb < 16; bb++) {
        float2 p = u2f(acc[bb]);
        part[warp * 528 + row * 33 + b0 + bb] = p.x + p.y;
    }
    __syncthreads();
    // pointwise: thread = (jj, b) for 4 j x 32 b
    if (tid < 128) {
        int jj = tid >> 5, b = tid & 31;
        float gv[4];
        #pragma unroll
        for (int g2 = 0; g2 < 4; g2++) {
            int ln = g2 * 4 + jj;
            float s = 0.f;
            #pragma unroll
            for (int w2 = 0; w2 < 8; w2++) s += part[w2 * 528 + ln * 33 + b];
            gv[g2] = s + d_cg[(g2 * H + blockIdx.x * 4 + jj) * B + b];
        }
        float ig = sigmoidf_(gv[0]);
        float fg = sigmoidf_(gv[1]);
        float gg = tanhf(gv[2]);
        float og = sigmoidf_(gv[3]);
        int jg = blockIdx.x * 4 + jj;
        float c = fg * d_cbuf[b * H + jg] + ig * gg;
        d_cbuf[b * H + jg] = c;
        d_hbuf[(t + 1) & 1][b * H + jg] = og * tanhf(c);
    }
}

// ---------------- per-step logits (K=768 part) + fused argmax ----------------
// 250 blocks x 128 thr (2 blocks/SM). Block = 128 v, b = 32, full K.
// Weights staged per 16-k chunk through smem; feature LDS explicitly
// software-pipelined with an 8-slot register ring (load->use distance ~24 instr
// covers the 29-cyc LDS latency with only 2 warps/SMSP).
__global__ __launch_bounds__(128, 2) void logitsK(int t, const int* __restrict__ y0,
        const float* __restrict__ emb, const float* __restrict__ Wout) {
    extern __shared__ float fs[];                 // B*768 feat | 128*WTLD weight tile
    float* wt = fs + B * 768;
    int* ys = (int*)wt;                           // alias: dead before wt written
    u64* red = (u64*)wt;                          // alias: wt dead after final chunk sync
    int tid = threadIdx.x;
    if (tid < B)
        ys[tid] = (t == 0) ? y0[tid]
                           : (int)(~(unsigned)(d_slot[(t - 1) * B + tid] & 0xFFFFFFFFull));
    __syncthreads();
    const float* hc = d_hbuf[(t + 1) & 1];
    for (int i = tid; i < B * (KF / 4); i += 128) {
        int b = i / (KF / 4), k = (i % (KF / 4)) * 4;
        float4 v = (k < E) ? *(const float4*)(emb + (long)ys[b] * E + k)
                           : *(const float4*)(hc + b * H + (k - E));
        *(float4*)(fs + b * 768 + k) = v;
    }
    __syncthreads();                              // ys reads done; wt region free
    int warp = tid >> 5, lane = tid & 31;
    int vl = warp * 32 + lane;
    int v = blockIdx.x * 128 + vl;
    // tile: 128 rows x 16 floats = 512 float4s; thread loads rows tid>>2 + {0,32,64,96}
    int q = tid & 3;
    int r0 = tid >> 2;
    const float* gbase = Wout + ((long)blockIdx.x * 128 + r0) * WOUT_LD + 512 + q * 4;
    const float* g1 = gbase;
    const float* g2 = gbase + 32 * WOUT_LD;
    const float* g3 = gbase + 64 * WOUT_LD;
    const float* g4 = gbase + 96 * WOUT_LD;
    float* s1 = wt + r0 * WTLD + q * 4;
    float* s2 = s1 + 32 * WTLD;
    float* s3 = s1 + 64 * WTLD;
    float* s4 = s1 + 96 * WTLD;
    u64 acc[32];
    #pragma unroll
    for (int i = 0; i < 32; i++) acc[i] = 0ULL;
    unsigned fsb = (unsigned)__cvta_generic_to_shared(fs);
    unsigned wlb = (unsigned)__cvta_generic_to_shared(wt + vl * WTLD);
    float4 p1 = *(const float4*)(g1);             // preload chunk 0
    float4 p2 = *(const float4*)(g2);
    float4 p3 = *(const float4*)(g3);
    float4 p4 = *(const float4*)(g4);
    for (int kb = 0; kb < KF; kb += 16) {
        *(float4*)s1 = p1;
        *(float4*)s2 = p2;
        *(float4*)s3 = p3;
        *(float4*)s4 = p4;
        __syncthreads();
        if (kb + 16 < KF) {                       // prefetch next chunk into regs
            p1 = *(const float4*)(g1 + kb + 16);
            p2 = *(const float4*)(g2 + kb + 16);
            p3 = *(const float4*)(g3 + kb + 16);
            p4 = *(const float4*)(g4 + kb + 16);
        }
        // weight pairs for the 4 k-groups of this chunk (own row, conflict-free)
        u64 wx[4], wy[4];
        #pragma unroll
        for (int i = 0; i < 4; i++) lds128(wx[i], wy[i], wlb + (unsigned)(i * 16));
        #pragma unroll
        for (int i = 0; i < 4; i++) {
            unsigned fb0 = fsb + (unsigned)(kb + i * 4) * 4u;
            u64 ra[8], rb[8];
            #pragma unroll
            for (int p = 0; p < 8; p++)
                lds128(ra[p], rb[p], fb0 + (unsigned)(p * 768) * 4u);
            #pragma unroll
            for (int b = 0; b < 32; b++) {
                int s = b & 7;
                acc[b] = fma2(wx[i], ra[s], acc[b]);
                acc[b] = fma2(wy[i], rb[s], acc[b]);
                if (b < 24)
                    lds128(ra[s], rb[s], fb0 + (unsigned)((b + 8) * 768) * 4u);
            }
        }
        __syncthreads();
    }
    // epilogue: add base, store (T,B,V), per-b argmax across lanes
    #pragma unroll
    for (int b = 0; b < 32; b++) {
        float2 p = u2f(acc[b]);
        float s = p.x + p.y + d_base[(long)b * VV + v];
        d_scratch[((long)t * B + b) * VV + v] = s;
        u64 pm = packmax(s, v);
        #pragma unroll
        for (int o = 16; o > 0; o >>= 1) {
            u64 qq = __shfl_xor_sync(0xffffffffu, pm, o);
            if (qq > pm) pm = qq;
        }
        if (lane == 0) red[warp * 32 + b] = pm;
    }
    __syncthreads();
    if (tid < B) {
        u64 m = red[tid];
        #pragma unroll
        for (int w = 1; w < 4; w++) if (red[w * 32 + tid] > m) m = red[w * 32 + tid];
        atomicMax(&d_slot[t * B + tid], m);
    }
}

// ---------------- final transpose (T, B, V) -> (B, V, T) ----------------
__global__ void transposeK(float* __restrict__ out) {
    __shared__ float tile[32][33];
    int b  = blockIdx.z;
    int vt = blockIdx.x;
    int tt = blockIdx.y;
    int tx = threadIdx.x, ty = threadIdx.y;   // (32, 8)
    #pragma unroll
    for (int i = 0; i < 32; i += 8) {
        int t = tt * 32 + ty + i;
        int v = vt * 32 + tx;
        tile[ty + i][tx] = d_scratch[((long)t * B + b) * VV + v];
    }
    __syncthreads();
    #pragma unroll
    for (int i = 0; i < 32; i += 8) {
        int v = vt * 32 + ty + i;
        int t = tt * 32 + tx;
        out[((long)b * VV + v) * TT + t] = tile[tx][ty + i];
    }
}

// ---------------- launch ----------------
extern "C" void kernel_launch(void* const* d_in, const int* in_sizes, int n_in,
                              void* d_out, int out_size) {
    const int*   y0   = (const int*)d_in[0];
    const float* h0   = (const float*)d_in[1];
    const float* c0   = (const float*)d_in[2];
    const float* emb  = (const float*)d_in[3];
    const float* Wih  = (const float*)d_in[4];
    const float* Whh  = (const float*)d_in[5];
    const float* bih  = (const float*)d_in[6];
    const float* bhh  = (const float*)d_in[7];
    const float* Wout = (const float*)d_in[8];
    const float* bout = (const float*)d_in[9];
    float* out = (float*)d_out;

    int smemL = (B * 768 + 128 * WTLD) * (int)sizeof(float);  // 108544 B -> 2 blocks/SM
    int smemG = (B * 768 + 8 * 528) * (int)sizeof(float);     // 115200 B
    int smemB = B * PADZ * (int)sizeof(float);                // 66048 B
    cudaFuncSetAttribute(logitsK, cudaFuncAttributeMaxDynamicSharedMemorySize, smemL);
    cudaFuncSetAttribute(gatesF,  cudaFuncAttributeMaxDynamicSharedMemorySize, smemG);
    cudaFuncSetAttribute(baseK,   cudaFuncAttributeMaxDynamicSharedMemorySize, smemB);

    initK<<<64, 256>>>(h0, c0);
    constgateK<<<8192, 256>>>(h0, Wih, bih, bhh);
    baseK<<<VV / 128, 128, smemB>>>(h0, Wout, bout);

    for (int t = 0; t < TT; t++) {
        gatesF<<<128, 256, smemG>>>(t, y0, emb, Wih, Whh);
        logitsK<<<VV / 128, 128, smemL>>>(t, y0, emb, Wout);
    }
    transposeK<<<dim3(VV / 32, TT / 32, B), dim3(32, 8)>>>(out);
}

// round 17
// speedup vs baseline: 1.5060x; 1.1981x over previous
#include <cuda_runtime.h>
#include <cuda_fp16.h>
#include <math.h>

#define B 32
#define H 512
#define E 256
#define VV 32000
#define TT 64
#define KF 768          // E + H (dynamic feature length)
#define WOUT_LD 1280    // 2H + E
#define PADZ 516        // H + 4 pad (baseK only)
#define FST 776         // F tile row stride in halves (768 + 8): conflict-free b-frag lds

typedef unsigned long long u64;

// ---------------- persistent device scratch (no allocations) ----------------
__device__ uint4  d_W2[250 * 6 * 4096];         // 98.3 MB: W_out fp16 hi/lo in A-fragment order
__device__ float  d_scratch[TT * B * VV];       // logits in (T, B, V) layout
__device__ float  d_base[B * VV];               // z @ W_out_z^T + b_out (exact fp32)
__device__ float  d_cg[4 * H * B];              // z @ W_ih_z^T + b_ih + b_hh
__device__ float  d_hbuf[2][B * H];
__device__ float  d_cbuf[B * H];
__device__ u64    d_slot[TT * B];               // packed (orderable(max) << 32) | ~argmax

__device__ __forceinline__ u64 packmax(float f, int v) {
    unsigned u = __float_as_uint(f);
    u = (u & 0x80000000u) ? ~u : (u | 0x80000000u);
    return ((u64)u << 32) | (unsigned)(~v);
}
__device__ __forceinline__ float sigmoidf_(float x) { return 1.0f / (1.0f + expf(-x)); }

__device__ __forceinline__ u64 fma2(u64 a, u64 b, u64 c) {
    u64 d;
    asm("fma.rn.f32x2 %0, %1, %2, %3;" : "=l"(d) : "l"(a), "l"(b), "l"(c));
    return d;
}
__device__ __forceinline__ float2 u2f(u64 v) {
    float2 r;
    asm("mov.b64 {%0, %1}, %2;" : "=f"(r.x), "=f"(r.y) : "l"(v));
    return r;
}
__device__ __forceinline__ void lds128(u64& a, u64& b, unsigned saddr) {
    asm("ld.shared.v2.u64 {%0, %1}, [%2];" : "=l"(a), "=l"(b) : "r"(saddr));
}
__device__ __forceinline__ unsigned packh(__half a, __half b) {
    return ((unsigned)__half_as_ushort(b) << 16) | (unsigned)__half_as_ushort(a);
}

// warp-level HMMA: D(16x8) += A(16x16 f16, row) * B(16x8 f16, col), fp32 accum
#define MMA(dd, aa, b0, b1) \
    asm volatile("mma.sync.aligned.m16n8k16.row.col.f32.f16.f16.f32 " \
        "{%0,%1,%2,%3}, {%4,%5,%6,%7}, {%8,%9}, {%0,%1,%2,%3};" \
        : "+f"((dd)[0]), "+f"((dd)[1]), "+f"((dd)[2]), "+f"((dd)[3]) \
        : "r"((aa).x), "r"((aa).y), "r"((aa).z), "r"((aa).w), "r"(b0), "r"(b1))

// ---------------- init ----------------
__global__ void initK(const float* __restrict__ h0, const float* __restrict__ c0) {
    int i = blockIdx.x * blockDim.x + threadIdx.x;
    if (i < B * H) { d_hbuf[0][i] = h0[i]; d_cbuf[i] = c0[i]; }
    if (i < TT * B) d_slot[i] = 0ULL;
}

// ---------------- one-time: bake W_out cols [512:1280) into fp16 hi/lo A-fragments ----------
// Fragment layout (m16n8k16, A row-major): lane = g*4+tg (g=lane>>2, tg=lane&3)
//   a.x: row g,   cols k0,k0+1   a.y: row g+8, cols k0,k0+1
//   a.z: row g,   cols k0+8,+9   a.w: row g+8, cols k0+8,+9      (k0 = ks*16 + tg*2)
__global__ __launch_bounds__(256) void prepW(const float* __restrict__ Wout) {
    __shared__ float ws[16 * 768];                // 48 KB patch: rows m*16.., cols 512..1280
    int m = blockIdx.x;                           // 0..1999 (vtile)
    int tid = threadIdx.x;
    for (int i = tid; i < 16 * 192; i += 256) {
        int r = i / 192, kq = (i % 192) * 4;
        *(float4*)(ws + r * 768 + kq) =
            *(const float4*)(Wout + (long)(m * 16 + r) * WOUT_LD + 512 + kq);
    }
    __syncthreads();
    for (int o = tid; o < 3072; o += 256) {       // 48 ks x 2 hl x 32 lane
        int lane = o & 31, hl = (o >> 5) & 1, ks = o >> 6;
        int g = lane >> 2, tg = lane & 3;
        int k0 = ks * 16 + tg * 2;
        float x[8];
        x[0] = ws[g * 768 + k0];       x[1] = ws[g * 768 + k0 + 1];
        x[2] = ws[(g + 8) * 768 + k0]; x[3] = ws[(g + 8) * 768 + k0 + 1];
        x[4] = ws[g * 768 + k0 + 8];   x[5] = ws[g * 768 + k0 + 9];
        x[6] = ws[(g + 8) * 768 + k0 + 8]; x[7] = ws[(g + 8) * 768 + k0 + 9];
        unsigned u[4];
        #pragma unroll
        for (int j = 0; j < 4; j++) {
            __half h0 = __float2half(x[2 * j]), h1 = __float2half(x[2 * j + 1]);
            if (hl) {
                h0 = __float2half(x[2 * j]     - __half2float(h0));
                h1 = __float2half(x[2 * j + 1] - __half2float(h1));
            }
            u[j] = packh(h0, h1);
        }
        d_W2[(((long)m * 48 + ks) * 2 + hl) * 32 + lane] = make_uint4(u[0], u[1], u[2], u[3]);
    }
}

// ---------------- precompute cg ----------------
__global__ void constgateK(const float* __restrict__ h0, const float* __restrict__ Wih,
                           const float* __restrict__ bih, const float* __restrict__ bhh) {
    int gw = (blockIdx.x * blockDim.x + threadIdx.x) >> 5;
    int lane = threadIdx.x & 31;
    int b = gw & 31;
    int R = gw >> 5;
    const float* z = h0 + b * H;
    const float* w = Wih + (long)R * KF;
    float a = 0.f;
    for (int k = lane; k < H; k += 32) a += w[k] * z[k];
    #pragma unroll
    for (int o = 16; o > 0; o >>= 1) a += __shfl_down_sync(0xffffffffu, a, o);
    if (lane == 0) d_cg[R * B + b] = a + bih[R] + bhh[R];
}

// ---------------- precompute base (exact fp32 z-part) ----------------
__global__ __launch_bounds__(128, 2) void baseK(const float* __restrict__ h0,
        const float* __restrict__ Wout, const float* __restrict__ bout) {
    extern __shared__ float zs[];
    int tid = threadIdx.x;
    for (int i = tid; i < B * (H / 4); i += 128) {
        int b = i / (H / 4), k = (i % (H / 4)) * 4;
        *(float4*)(zs + b * PADZ + k) = *(const float4*)(h0 + b * H + k);
    }
    __syncthreads();
    int warp = tid >> 5, lane = tid & 31;
    int v = blockIdx.x * 128 + warp * 32 + lane;
    const float* wrow = Wout + (long)v * WOUT_LD;
    u64 acc[32];
    #pragma unroll
    for (int i = 0; i < 32; i++) acc[i] = 0ULL;
    unsigned zsb = (unsigned)__cvta_generic_to_shared(zs);
    for (int kb = 0; kb < H; kb += 16) {
        ulonglong2 w[4];
        #pragma unroll
        for (int i = 0; i < 4; i++) w[i] = *(const ulonglong2*)(wrow + kb + i * 4);
        #pragma unroll
        for (int i = 0; i < 4; i++) {
            #pragma unroll
            for (int b = 0; b < 32; b++) {
                u64 fa, fb;
                lds128(fa, fb, zsb + (unsigned)(b * PADZ + kb + i * 4) * 4u);
                acc[b] = fma2(w[i].x, fa, acc[b]);
                acc[b] = fma2(w[i].y, fb, acc[b]);
            }
        }
    }
    float bo = bout[v];
    #pragma unroll
    for (int b = 0; b < 32; b++) {
        float2 p = u2f(acc[b]);
        d_base[(long)b * VV + v] = p.x + p.y + bo;
    }
}

// ---------------- per-step fused LSTM gates (unchanged, R13-passing) ----------------
__global__ __launch_bounds__(256) void gatesF(int t, const int* __restrict__ y0,
        const float* __restrict__ emb, const float* __restrict__ Wih,
        const float* __restrict__ Whh) {
    extern __shared__ float fs[];
    float* part = fs + B * 768;
    int* ys = (int*)part;
    int tid = threadIdx.x;
    if (tid < B)
        ys[tid] = (t == 0) ? y0[tid]
                           : (int)(~(unsigned)(d_slot[(t - 1) * B + tid] & 0xFFFFFFFFull));
    __syncthreads();
    const float* hold = d_hbuf[t & 1];
    for (int i = tid; i < B * (KF / 4); i += 256) {
        int b = i / (KF / 4), k = (i % (KF / 4)) * 4;
        float4 v = (k < E) ? *(const float4*)(emb + (long)ys[b] * E + k)
                           : *(const float4*)(hold + b * H + (k - E));
        *(float4*)(fs + b * 768 + k) = v;
    }
    __syncthreads();
    int warp = tid >> 5, lane = tid & 31;
    int row = lane >> 1, bh = lane & 1, b0 = bh << 4;
    int g = row >> 2, jl = row & 3;
    int j = blockIdx.x * 4 + jl;
    int R = g * H + j;
    int klo = warp * 96;
    u64 acc[16];
    #pragma unroll
    for (int i = 0; i < 16; i++) acc[i] = 0ULL;
    unsigned fsb = (unsigned)__cvta_generic_to_shared(fs);
    const float* w1  = Wih + (long)R * KF + 512;
    const float* w2p = Whh + (long)R * H - E;
    ulonglong2 w[4], wn[4];
    {
        const float* wp = (klo < E) ? (w1 + klo) : (w2p + klo);
        #pragma unroll
        for (int i = 0; i < 4; i++) w[i] = *(const ulonglong2*)(wp + i * 4);
    }
    for (int kc = klo; kc < klo + 96; kc += 16) {
        int kn = kc + 16;
        if (kn < klo + 96) {
            const float* wq = (kn < E) ? (w1 + kn) : (w2p + kn);
            #pragma unroll
            for (int i = 0; i < 4; i++) wn[i] = *(const ulonglong2*)(wq + i * 4);
        }
        #pragma unroll
        for (int i = 0; i < 4; i++) {
            #pragma unroll
            for (int bb = 0; bb < 16; bb++) {
                u64 fa, fb;
                lds128(fa, fb, fsb + (unsigned)((b0 + bb) * 768 + kc + i * 4) * 4u);
                acc[bb] = fma2(w[i].x, fa, acc[bb]);
                acc[bb] = fma2(w[i].y, fb, acc[bb]);
            }
        }
        #pragma unroll
        for (int i = 0; i < 4; i++) w[i] = wn[i];
    }
    #pragma unroll
    for (int bb = 0; bb < 16; bb++) {
        float2 p = u2f(acc[bb]);
        part[warp * 528 + row * 33 + b0 + bb] = p.x + p.y;
    }
    __syncthreads();
    if (tid < 128) {
        int jj = tid >> 5, b = tid & 31;
        float gv[4];
        #pragma unroll
        for (int g2 = 0; g2 < 4; g2++) {
            int ln = g2 * 4 + jj;
            float s = 0.f;
            #pragma unroll
            for (int w2 = 0; w2 < 8; w2++) s += part[w2 * 528 + ln * 33 + b];
            gv[g2] = s + d_cg[(g2 * H + blockIdx.x * 4 + jj) * B + b];
        }
        float ig = sigmoidf_(gv[0]);
        float fg = sigmoidf_(gv[1]);
        float gg = tanhf(gv[2]);
        float og = sigmoidf_(gv[3]);
        int jg = blockIdx.x * 4 + jj;
        float c = fg * d_cbuf[b * H + jg] + ig * gg;
        d_cbuf[b * H + jg] = c;
        d_hbuf[(t + 1) & 1][b * H + jg] = og * tanhf(c);
    }
}

// ---------------- per-step logits: mma.sync f16-split GEMM + fused argmax ----------------
// 250 blocks x 128 thr (4 warps). Block = 128 v x 32 b. Warp = 2 m-tiles x 4 n-tiles.
// K = 48 steps of 16. Passes: Whi*Fhi + Whi*Flo + Wlo*Fhi (lo*lo dropped, ~2^-22).
#define SM_FHI 0
#define SM_FLO (32 * FST * 2)                    // 49664
#define SM_DB  (SM_FLO + 32 * FST * 2)           // 99328
#define SMEM_M (SM_DB + 32 * 132 * 4)            // 116224 B

#define LOADA(A, ks) do { \
    (A)[0] = wp[(((long)(mbase)     * 48 + (ks)) * 2 + 0) * 32]; \
    (A)[1] = wp[(((long)(mbase)     * 48 + (ks)) * 2 + 1) * 32]; \
    (A)[2] = wp[(((long)(mbase + 1) * 48 + (ks)) * 2 + 0) * 32]; \
    (A)[3] = wp[(((long)(mbase + 1) * 48 + (ks)) * 2 + 1) * 32]; \
} while (0)

#define DOMMA(ks, A) do { \
    unsigned bh[4][2], bl[4][2]; \
    _Pragma("unroll") \
    for (int nt = 0; nt < 4; nt++) { \
        const __half* ph = fhi + (nt * 8 + g) * FST + (ks) * 16 + tg * 2; \
        const __half* pl = flo + (nt * 8 + g) * FST + (ks) * 16 + tg * 2; \
        bh[nt][0] = *(const unsigned*)ph;       bh[nt][1] = *(const unsigned*)(ph + 8); \
        bl[nt][0] = *(const unsigned*)pl;       bl[nt][1] = *(const unsigned*)(pl + 8); \
    } \
    _Pragma("unroll") \
    for (int mm = 0; mm < 2; mm++) { \
        _Pragma("unroll") \
        for (int nt = 0; nt < 4; nt++) { \
            MMA(d[mm][nt], (A)[mm * 2 + 0], bh[nt][0], bh[nt][1]); \
            MMA(d[mm][nt], (A)[mm * 2 + 0], bl[nt][0], bl[nt][1]); \
            MMA(d[mm][nt], (A)[mm * 2 + 1], bh[nt][0], bh[nt][1]); \
        } \
    } \
} while (0)

__global__ __launch_bounds__(128, 1) void logitsM(int t, const int* __restrict__ y0,
        const float* __restrict__ emb) {
    extern __shared__ unsigned char sm[];
    __half* fhi = (__half*)(sm + SM_FHI);
    __half* flo = (__half*)(sm + SM_FLO);
    float* dbuf = (float*)(sm + SM_DB);
    __shared__ int ys[B];
    __shared__ u64 red[4][B];
    int tid = threadIdx.x, w = tid >> 5, lane = tid & 31;
    int g = lane >> 2, tg = lane & 3;
    if (tid < B)
        ys[tid] = (t == 0) ? y0[tid]
                           : (int)(~(unsigned)(d_slot[(t - 1) * B + tid] & 0xFFFFFFFFull));
    __syncthreads();
    // build F hi/lo tiles: feat[b][k] = [emb[y_b] | h_b]
    const float* hc = d_hbuf[(t + 1) & 1];
    for (int i = tid; i < B * 192; i += 128) {
        int b = i / 192, k0 = (i % 192) * 4;
        float4 v = (k0 < E) ? *(const float4*)(emb + (long)ys[b] * E + k0)
                            : *(const float4*)(hc + b * H + (k0 - E));
        __half h0 = __float2half(v.x), h1 = __float2half(v.y);
        __half h2 = __float2half(v.z), h3 = __float2half(v.w);
        __half l0 = __float2half(v.x - __half2float(h0));
        __half l1 = __float2half(v.y - __half2float(h1));
        __half l2 = __float2half(v.z - __half2float(h2));
        __half l3 = __float2half(v.w - __half2float(h3));
        unsigned* ph = (unsigned*)(fhi + b * FST + k0);
        unsigned* pl = (unsigned*)(flo + b * FST + k0);
        ph[0] = packh(h0, h1); ph[1] = packh(h2, h3);
        pl[0] = packh(l0, l1); pl[1] = packh(l2, l3);
    }
    __syncthreads();

    int mbase = blockIdx.x * 8 + w * 2;
    const uint4* wp = d_W2 + lane;
    float d[2][4][4];
    #pragma unroll
    for (int mm = 0; mm < 2; mm++)
        #pragma unroll
        for (int nt = 0; nt < 4; nt++)
            #pragma unroll
            for (int c = 0; c < 4; c++) d[mm][nt][c] = 0.f;

    uint4 A0[4], A1[4], A2[4];
    LOADA(A0, 0);
    LOADA(A1, 1);
    for (int kb = 0; kb < 48; kb += 3) {
        if (kb + 2 < 48) LOADA(A2, kb + 2);
        DOMMA(kb, A0);
        if (kb + 3 < 48) LOADA(A0, kb + 3);
        DOMMA(kb + 1, A1);
        if (kb + 4 < 48) LOADA(A1, kb + 4);
        DOMMA(kb + 2, A2);
    }

    // D frags -> smem staging (stride 132: conflict-free)
    #pragma unroll
    for (int mm = 0; mm < 2; mm++)
        #pragma unroll
        for (int nt = 0; nt < 4; nt++)
            #pragma unroll
            for (int c = 0; c < 4; c++) {
                int vl = w * 32 + mm * 16 + g + ((c >> 1) << 3);
                int b  = nt * 8 + tg * 2 + (c & 1);
                dbuf[b * 132 + vl] = d[mm][nt][c];
            }
    __syncthreads();

    // epilogue: add base, store (T,B,V), per-b argmax across lanes
    int v = blockIdx.x * 128 + w * 32 + lane;
    #pragma unroll
    for (int b = 0; b < B; b++) {
        float s = dbuf[b * 132 + w * 32 + lane] + d_base[(long)b * VV + v];
        d_scratch[((long)t * B + b) * VV + v] = s;
        u64 pm = packmax(s, v);
        #pragma unroll
        for (int o = 16; o > 0; o >>= 1) {
            u64 q = __shfl_xor_sync(0xffffffffu, pm, o);
            if (q > pm) pm = q;
        }
        if (lane == 0) red[w][b] = pm;
    }
    __syncthreads();
    if (tid < B) {
        u64 m = red[0][tid];
        #pragma unroll
        for (int w2 = 1; w2 < 4; w2++) if (red[w2][tid] > m) m = red[w2][tid];
        atomicMax(&d_slot[t * B + tid], m);
    }
}

// ---------------- final transpose (T, B, V) -> (B, V, T) ----------------
__global__ void transposeK(float* __restrict__ out) {
    __shared__ float tile[32][33];
    int b  = blockIdx.z;
    int vt = blockIdx.x;
    int tt = blockIdx.y;
    int tx = threadIdx.x, ty = threadIdx.y;   // (32, 8)
    #pragma unroll
    for (int i = 0; i < 32; i += 8) {
        int t = tt * 32 + ty + i;
        int v = vt * 32 + tx;
        tile[ty + i][tx] = d_scratch[((long)t * B + b) * VV + v];
    }
    __syncthreads();
    #pragma unroll
    for (int i = 0; i < 32; i += 8) {
        int v = vt * 32 + ty + i;
        int t = tt * 32 + tx;
        out[((long)b * VV + v) * TT + t] = tile[tx][ty + i];
    }
}

// ---------------- launch ----------------
extern "C" void kernel_launch(void* const* d_in, const int* in_sizes, int n_in,
                              void* d_out, int out_size) {
    const int*   y0   = (const int*)d_in[0];
    const float* h0   = (const float*)d_in[1];
    const float* c0   = (const float*)d_in[2];
    const float* emb  = (const float*)d_in[3];
    const float* Wih  = (const float*)d_in[4];
    const float* Whh  = (const float*)d_in[5];
    const float* bih  = (const float*)d_in[6];
    const float* bhh  = (const float*)d_in[7];
    const float* Wout = (const float*)d_in[8];
    const float* bout = (const float*)d_in[9];
    float* out = (float*)d_out;

    int smemG = (B * 768 + 8 * 528) * (int)sizeof(float);     // 115200 B
    int smemB = B * PADZ * (int)sizeof(float);                // 66048 B
    cudaFuncSetAttribute(gatesF,  cudaFuncAttributeMaxDynamicSharedMemorySize, smemG);
    cudaFuncSetAttribute(baseK,   cudaFuncAttributeMaxDynamicSharedMemorySize, smemB);
    cudaFuncSetAttribute(logitsM, cudaFuncAttributeMaxDynamicSharedMemorySize, SMEM_M);

    initK<<<64, 256>>>(h0, c0);
    prepW<<<2000, 256>>>(Wout);
    constgateK<<<8192, 256>>>(h0, Wih, bih, bhh);
    baseK<<<VV / 128, 128, smemB>>>(h0, Wout, bout);

    for (int t = 0; t < TT; t++) {
        gatesF<<<128, 256, smemG>>>(t, y0, emb, Wih, Whh);
        logitsM<<<250, 128, SMEM_M>>>(t, y0, emb);
    }
    transposeK<<<dim3(VV / 32, TT / 32, B), dim3(32, 8)>>>(out);
}